// round 7
// baseline (speedup 1.0000x reference)
#include <cuda_runtime.h>
#include <cuda_bf16.h>
#include <cstdint>

static constexpr int Bn = 2;
static constexpr int Ln = 2048;
static constexpr int Dn = 1536;
static constexpr int NTILE = Ln / 128;                 // 16 col-tiles
static constexpr int NSUP  = Ln / 256;                 // 8 row-supertiles
static constexpr int NPAIR2 = 72;                      // sum_{a<8}(16-2a)
static constexpr int BK = 32;                          // k per stage
static constexpr int NSTG = Dn / BK;                   // 48
static constexpr int A_TILE_B = 256 * BK * 2;          // 16384 B per A plane
static constexpr int B_TILE_B = 128 * BK * 2;          // 8192 B per B plane
static constexpr int STAGE_B = 2 * A_TILE_B + 2 * B_TILE_B;  // 49152
static constexpr int NSTAGE = 3;
static constexpr int SMEM_DYN = NSTAGE * STAGE_B;      // 147456

// bf16 planes: 0..7 = H*Wp_t split (b*4 + t*2 + {hi,lo}); 8..11 = H split (8 + b*2 + {hi,lo})
__device__ __align__(16) __nv_bfloat16 g_cvt[12ull * Ln * Dn];

// ---------------------------------------------------------------- convert
__global__ __launch_bounds__(256) void cvt_kernel(const float* __restrict__ H,
                                                  const float* __restrict__ W)
{
    const int idx = blockIdx.x * 256 + threadIdx.x;
    const int d4  = idx % (Dn / 4);
    const int row = (idx / (Dn / 4)) % Ln;
    const int b   = idx / ((Dn / 4) * Ln);
    const int d0  = d4 * 4;

    const float4 h = *reinterpret_cast<const float4*>(H + ((size_t)b * Ln + row) * Dn + d0);
    const size_t rowoff = (size_t)row * Dn + d0;

    auto store_split = [&](int plane_hi, float4 v) {
        float a[4] = {v.x, v.y, v.z, v.w};
        __nv_bfloat16 hi[4], lo[4];
#pragma unroll
        for (int i = 0; i < 4; ++i) {
            hi[i] = __float2bfloat16(a[i]);
            lo[i] = __float2bfloat16(a[i] - __bfloat162float(hi[i]));
        }
        __nv_bfloat162* ph = reinterpret_cast<__nv_bfloat162*>(
            g_cvt + (size_t)plane_hi * Ln * Dn + rowoff);
        __nv_bfloat162* pl = reinterpret_cast<__nv_bfloat162*>(
            g_cvt + (size_t)(plane_hi + 1) * Ln * Dn + rowoff);
        ph[0] = __nv_bfloat162(hi[0], hi[1]);
        ph[1] = __nv_bfloat162(hi[2], hi[3]);
        pl[0] = __nv_bfloat162(lo[0], lo[1]);
        pl[1] = __nv_bfloat162(lo[2], lo[3]);
    };

#pragma unroll
    for (int t = 0; t < 2; ++t) {
        const float4 w = *reinterpret_cast<const float4*>(W + (size_t)t * (2 * Dn) + d0);
        store_split(b * 4 + t * 2, make_float4(h.x * w.x, h.y * w.y, h.z * w.z, h.w * w.w));
    }
    store_split(8 + b * 2, h);
}

// ---------------------------------------------------------------- helpers
__device__ __forceinline__ uint32_t s2u(const void* p) {
    uint32_t a;
    asm("{ .reg .u64 t; cvta.to.shared.u64 t, %1; cvt.u32.u64 %0, t; }" : "=r"(a) : "l"(p));
    return a;
}

// swizzled byte offset in a (rows x 32 bf16) tile: row*64 + (c ^ ((row>>1)&3))*16
__device__ __forceinline__ uint32_t swz(int row, int c) {
    return (uint32_t)(row * 64 + ((c ^ ((row >> 1) & 3)) << 4));
}

#define LDSM4(R0, R1, R2, R3, addr)                                            \
    asm volatile("ldmatrix.sync.aligned.m8n8.x4.shared.b16 {%0,%1,%2,%3}, [%4];" \
                 : "=r"(R0), "=r"(R1), "=r"(R2), "=r"(R3) : "r"(addr))

#define MMA(C, A, B)                                                              \
    asm volatile(                                                                 \
        "mma.sync.aligned.m16n8k16.row.col.f32.bf16.bf16.f32 "                    \
        "{%0,%1,%2,%3},{%4,%5,%6,%7},{%8,%9},{%0,%1,%2,%3};"                      \
        : "+f"((C)[0]), "+f"((C)[1]), "+f"((C)[2]), "+f"((C)[3])                  \
        : "r"((A)[0]), "r"((A)[1]), "r"((A)[2]), "r"((A)[3]),                     \
          "r"((B)[0]), "r"((B)[1]))

// ---------------------------------------------------------------- gram GEMM
// 256 threads, 8 warps in 4(m)x2(n), warp tile 64x64, CTA tile 256x128
__global__ __launch_bounds__(256, 1)
void gram_hmma(const float* __restrict__ bias, float* __restrict__ out)
{
    extern __shared__ __align__(1024) char smem_raw[];
    const uint32_t sb = s2u(smem_raw);

    const int tid = threadIdx.x;
    const int wid = tid >> 5;
    const int lane = tid & 31;

    const int wm = (wid >> 1) * 64;   // 0,64,128,192
    const int wn = (wid & 1) * 64;    // 0,64

    const int a_row = lane & 15;
    const int ak3   = lane >> 4;
    const int b_row = (lane & 7) + (lane >> 4) * 8;
    const int bk3   = (lane >> 3) & 1;

    // decode (supertile a, col-tile j), j in [2a, 15]
    int rem = blockIdx.x, a = 0;
    while (rem >= NTILE - 2 * a) { rem -= NTILE - 2 * a; ++a; }
    const int j = 2 * a + rem;
    const int b = blockIdx.y;
    const int t = blockIdx.z;
    const int gi0 = a * 256, gj0 = j * 128;
    const bool mirror = (j >= 2 * a + 2);

    const __nv_bfloat16* srcA[2];
    const __nv_bfloat16* srcB[2];
    srcA[0] = g_cvt + ((size_t)(b * 4 + t * 2) * Ln + gi0) * Dn;      // A hi
    srcA[1] = srcA[0] + (size_t)Ln * Dn;                               // A lo
    srcB[0] = g_cvt + ((size_t)(8 + b * 2) * Ln + gj0) * Dn;           // B hi
    srcB[1] = srcB[0] + (size_t)Ln * Dn;                               // B lo

    const int ld_row0 = tid >> 2, ld_c = tid & 3;

    auto load_stage = [&](int s, int buf) {
        const int k0 = s * BK;
        const uint32_t sbase = sb + buf * STAGE_B;
        // A planes: 256 rows each
#pragma unroll
        for (int pI = 0; pI < 2; ++pI) {
            const __nv_bfloat16* base = srcA[pI] + k0;
            const uint32_t tb = sbase + pI * A_TILE_B;
#pragma unroll
            for (int c2 = 0; c2 < 4; ++c2) {
                const int row = ld_row0 + c2 * 64;
                const uint32_t d = tb + swz(row, ld_c);
                const void* g = base + (size_t)row * Dn + ld_c * 8;
                asm volatile("cp.async.cg.shared.global [%0], [%1], 16;"
                             :: "r"(d), "l"(g) : "memory");
            }
        }
        // B planes: 128 rows each
#pragma unroll
        for (int pI = 0; pI < 2; ++pI) {
            const __nv_bfloat16* base = srcB[pI] + k0;
            const uint32_t tb = sbase + 2 * A_TILE_B + pI * B_TILE_B;
#pragma unroll
            for (int c2 = 0; c2 < 2; ++c2) {
                const int row = ld_row0 + c2 * 64;
                const uint32_t d = tb + swz(row, ld_c);
                const void* g = base + (size_t)row * Dn + ld_c * 8;
                asm volatile("cp.async.cg.shared.global [%0], [%1], 16;"
                             :: "r"(d), "l"(g) : "memory");
            }
        }
        asm volatile("cp.async.commit_group;" ::: "memory");
    };

    float acc[4][8][4];
#pragma unroll
    for (int mt = 0; mt < 4; ++mt)
#pragma unroll
        for (int nt = 0; nt < 8; ++nt)
#pragma unroll
            for (int e = 0; e < 4; ++e) acc[mt][nt][e] = 0.f;

    load_stage(0, 0);
    load_stage(1, 1);

#pragma unroll 1
    for (int s = 0; s < NSTG; ++s) {
        const int buf = s % NSTAGE;
        if (s == NSTG - 1)
            asm volatile("cp.async.wait_group 0;" ::: "memory");
        else
            asm volatile("cp.async.wait_group 1;" ::: "memory");
        __syncthreads();
        if (s + 2 < NSTG) load_stage(s + 2, (s + 2) % NSTAGE);

        const uint32_t Ah = sb + buf * STAGE_B;
        const uint32_t Al = Ah + A_TILE_B;
        const uint32_t Bh = Ah + 2 * A_TILE_B;
        const uint32_t Bl = Bh + B_TILE_B;

#pragma unroll
        for (int s16 = 0; s16 < 2; ++s16) {
            const int ca = s16 * 2 + ak3;
            const int cb = s16 * 2 + bk3;

            uint32_t bh[8][2], bl[8][2], ah[4][4];
#pragma unroll
            for (int n2 = 0; n2 < 4; ++n2) {
                const int rB = wn + n2 * 16 + b_row;
                uint32_t addr = Bh + swz(rB, cb);
                LDSM4(bh[n2 * 2][0], bh[n2 * 2][1], bh[n2 * 2 + 1][0], bh[n2 * 2 + 1][1], addr);
                addr = Bl + swz(rB, cb);
                LDSM4(bl[n2 * 2][0], bl[n2 * 2][1], bl[n2 * 2 + 1][0], bl[n2 * 2 + 1][1], addr);
            }
#pragma unroll
            for (int mt = 0; mt < 4; ++mt) {
                const int rA = wm + mt * 16 + a_row;
                LDSM4(ah[mt][0], ah[mt][1], ah[mt][2], ah[mt][3], Ah + swz(rA, ca));
            }

            // hi x hi
#pragma unroll
            for (int nt = 0; nt < 8; ++nt)
#pragma unroll
                for (int mt = 0; mt < 4; ++mt)
                    MMA(acc[mt][nt], ah[mt], bh[nt]);

            // hi x lo (reuse ah)
#pragma unroll
            for (int nt = 0; nt < 8; ++nt)
#pragma unroll
                for (int mt = 0; mt < 4; ++mt)
                    MMA(acc[mt][nt], ah[mt], bl[nt]);

            // lo x hi
            uint32_t al[4][4];
#pragma unroll
            for (int mt = 0; mt < 4; ++mt) {
                const int rA = wm + mt * 16 + a_row;
                LDSM4(al[mt][0], al[mt][1], al[mt][2], al[mt][3], Al + swz(rA, ca));
            }
#pragma unroll
            for (int nt = 0; nt < 8; ++nt)
#pragma unroll
                for (int mt = 0; mt < 4; ++mt)
                    MMA(acc[mt][nt], al[mt], bh[nt]);
        }
    }

    // ------------------------------------------------------------ epilogue
    const float bt = __ldg(&bias[t]);
    float* o = out + ((size_t)b * Ln * Ln) * 2 + t;
    const int r4 = lane >> 2;
    const int c4 = (lane & 3) * 2;

#pragma unroll
    for (int mt = 0; mt < 4; ++mt) {
#pragma unroll
        for (int nt = 0; nt < 8; ++nt) {
            const int i0 = gi0 + wm + mt * 16 + r4;
            const int j0 = gj0 + wn + nt * 8 + c4;
            const float v0 = acc[mt][nt][0] + bt;
            const float v1 = acc[mt][nt][1] + bt;
            const float v2 = acc[mt][nt][2] + bt;
            const float v3 = acc[mt][nt][3] + bt;
            o[((size_t)i0 * Ln + j0) * 2]           = v0;
            o[((size_t)i0 * Ln + j0 + 1) * 2]       = v1;
            o[((size_t)(i0 + 8) * Ln + j0) * 2]     = v2;
            o[((size_t)(i0 + 8) * Ln + j0 + 1) * 2] = v3;
            if (mirror) {
                o[((size_t)j0 * Ln + i0) * 2]           = v0;
                o[((size_t)(j0 + 1) * Ln + i0) * 2]     = v1;
                o[((size_t)j0 * Ln + i0 + 8) * 2]       = v2;
                o[((size_t)(j0 + 1) * Ln + i0 + 8) * 2] = v3;
            }
        }
    }
}

// ---------------------------------------------------------------- launch
extern "C" void kernel_launch(void* const* d_in, const int* in_sizes, int n_in,
                              void* d_out, int out_size)
{
    const float* H    = (const float*)d_in[0];
    const float* W    = (const float*)d_in[1];
    const float* bias = (const float*)d_in[2];
    float* out = (float*)d_out;

    cudaFuncSetAttribute(gram_hmma, cudaFuncAttributeMaxDynamicSharedMemorySize, SMEM_DYN);

    cvt_kernel<<<(Bn * Ln * (Dn / 4)) / 256, 256>>>(H, W);

    dim3 grid(NPAIR2, Bn, 2);
    gram_hmma<<<grid, 256, SMEM_DYN>>>(bias, out);
}

// round 9
// speedup vs baseline: 2.2970x; 2.2970x over previous
#include <cuda_runtime.h>
#include <cuda_fp16.h>
#include <cstdint>

static constexpr int Bn = 2;
static constexpr int Ln = 2048;
static constexpr int Dn = 1536;
static constexpr int NTILE = Ln / 128;                 // 16
static constexpr int NPAIR = NTILE * (NTILE + 1) / 2;  // 136
static constexpr int BK = 32;                          // k per stage
static constexpr int NSTG = Dn / BK;                   // 48
static constexpr int TILE_B = 128 * BK * 2;            // 8192 B per tile
static constexpr int STAGE_B = 3 * TILE_B;             // A0 + A1 + B = 24576
static constexpr int NSTAGE = 3;
static constexpr int SMEM_DYN = NSTAGE * STAGE_B;      // 73728

// f16 planes: 0..3 = A(b,t) = H*Wp_t  (index b*2+t); 4..5 = B(b) = H (index 4+b)
__device__ __align__(16) __half g_cvt[6ull * Ln * Dn];

// ---------------------------------------------------------------- convert
__global__ __launch_bounds__(256) void cvt_kernel(const float* __restrict__ H,
                                                  const float* __restrict__ W)
{
    const int idx = blockIdx.x * 256 + threadIdx.x;   // Bn*Ln*(Dn/4)
    const int d4  = idx % (Dn / 4);
    const int row = (idx / (Dn / 4)) % Ln;
    const int b   = idx / ((Dn / 4) * Ln);
    const int d0  = d4 * 4;

    const float4 h = *reinterpret_cast<const float4*>(H + ((size_t)b * Ln + row) * Dn + d0);
    const size_t rowoff = (size_t)row * Dn + d0;

#pragma unroll
    for (int t = 0; t < 2; ++t) {
        const float4 w = *reinterpret_cast<const float4*>(W + (size_t)t * (2 * Dn) + d0);
        __half2* p = reinterpret_cast<__half2*>(g_cvt + (size_t)(b * 2 + t) * Ln * Dn + rowoff);
        p[0] = __floats2half2_rn(h.x * w.x, h.y * w.y);
        p[1] = __floats2half2_rn(h.z * w.z, h.w * w.w);
    }
    __half2* q = reinterpret_cast<__half2*>(g_cvt + (size_t)(4 + b) * Ln * Dn + rowoff);
    q[0] = __floats2half2_rn(h.x, h.y);
    q[1] = __floats2half2_rn(h.z, h.w);
}

// ---------------------------------------------------------------- helpers
__device__ __forceinline__ uint32_t s2u(const void* p) {
    uint32_t a;
    asm("{ .reg .u64 t; cvta.to.shared.u64 t, %1; cvt.u32.u64 %0, t; }" : "=r"(a) : "l"(p));
    return a;
}

// swizzled byte offset inside a 128x32(f16) tile: row*64 + (c ^ ((row>>1)&3))*16
__device__ __forceinline__ uint32_t swz(int row, int c) {
    return (uint32_t)(row * 64 + ((c ^ ((row >> 1) & 3)) << 4));
}

#define LDSM4(R0, R1, R2, R3, addr)                                            \
    asm volatile("ldmatrix.sync.aligned.m8n8.x4.shared.b16 {%0,%1,%2,%3}, [%4];" \
                 : "=r"(R0), "=r"(R1), "=r"(R2), "=r"(R3) : "r"(addr))

#define MMA(C, A, B)                                                              \
    asm volatile(                                                                 \
        "mma.sync.aligned.m16n8k16.row.col.f32.f16.f16.f32 "                      \
        "{%0,%1,%2,%3},{%4,%5,%6,%7},{%8,%9},{%0,%1,%2,%3};"                      \
        : "+f"((C)[0]), "+f"((C)[1]), "+f"((C)[2]), "+f"((C)[3])                  \
        : "r"((A)[0]), "r"((A)[1]), "r"((A)[2]), "r"((A)[3]),                     \
          "r"((B)[0]), "r"((B)[1]))

// ---------------------------------------------------------------- gram GEMM
// 512 threads = 16 warps in 4(m)x4(n), warp tile 32x32 PER t (computes both t)
__global__ __launch_bounds__(512, 1)
void gram_hmma(const float* __restrict__ bias, float* __restrict__ out)
{
    extern __shared__ __align__(1024) char smem_raw[];
    const uint32_t sb = s2u(smem_raw);

    const int tid = threadIdx.x;
    const int wid = tid >> 5;
    const int lane = tid & 31;

    const int wm = (wid >> 2) * 32;   // 0,32,64,96
    const int wn = (wid & 3) * 32;    // 0,32,64,96

    const int a_row = lane & 15;
    const int ak3   = lane >> 4;
    const int b_row = (lane & 7) + (lane >> 4) * 8;
    const int bk3   = (lane >> 3) & 1;

    // decode upper-triangular tile pair (ti <= tj)
    int rem = blockIdx.x, ti = 0, rl = NTILE;
    while (rem >= rl) { rem -= rl; --rl; ++ti; }
    const int tj = ti + rem;
    const int b = blockIdx.y;
    const int gi0 = ti * 128, gj0 = tj * 128;
    const bool mirror = (ti != tj);

    const __half* src[3];
    src[0] = g_cvt + ((size_t)(b * 2 + 0) * Ln + gi0) * Dn;   // A t0
    src[1] = g_cvt + ((size_t)(b * 2 + 1) * Ln + gi0) * Dn;   // A t1
    src[2] = g_cvt + ((size_t)(4 + b) * Ln + gj0) * Dn;       // B

    // 512 threads: one 16B chunk per thread per tile (128 rows x 4 chunks)
    const int ld_row = tid >> 2, ld_c = tid & 3;

    auto load_stage = [&](int s, int buf) {
        const int k0 = s * BK;
        const uint32_t sbase = sb + buf * STAGE_B;
#pragma unroll
        for (int tI = 0; tI < 3; ++tI) {
            const __half* base = src[tI] + k0;
            const uint32_t d = sbase + tI * TILE_B + swz(ld_row, ld_c);
            const void* g = base + (size_t)ld_row * Dn + ld_c * 8;
            asm volatile("cp.async.cg.shared.global [%0], [%1], 16;"
                         :: "r"(d), "l"(g) : "memory");
        }
        asm volatile("cp.async.commit_group;" ::: "memory");
    };

    float acc[2][2][4][4];
#pragma unroll
    for (int t = 0; t < 2; ++t)
#pragma unroll
        for (int mt = 0; mt < 2; ++mt)
#pragma unroll
            for (int nt = 0; nt < 4; ++nt)
#pragma unroll
                for (int e = 0; e < 4; ++e) acc[t][mt][nt][e] = 0.f;

    load_stage(0, 0);
    load_stage(1, 1);

#pragma unroll 1
    for (int s = 0; s < NSTG; ++s) {
        const int buf = s % NSTAGE;
        if (s == NSTG - 1)
            asm volatile("cp.async.wait_group 0;" ::: "memory");
        else
            asm volatile("cp.async.wait_group 1;" ::: "memory");
        __syncthreads();
        if (s + 2 < NSTG) load_stage(s + 2, (s + 2) % NSTAGE);

        const uint32_t A0 = sb + buf * STAGE_B;
        const uint32_t A1 = A0 + TILE_B;
        const uint32_t Bt = A0 + 2 * TILE_B;

#pragma unroll
        for (int s16 = 0; s16 < 2; ++s16) {
            const int ca = s16 * 2 + ak3;
            const int cb = s16 * 2 + bk3;

            uint32_t bh[4][2], a0[2][4], a1[2][4];
#pragma unroll
            for (int n2 = 0; n2 < 2; ++n2) {
                const int rB = wn + n2 * 16 + b_row;
                LDSM4(bh[n2 * 2][0], bh[n2 * 2][1], bh[n2 * 2 + 1][0], bh[n2 * 2 + 1][1],
                      Bt + swz(rB, cb));
            }
#pragma unroll
            for (int mt = 0; mt < 2; ++mt) {
                const int rA = wm + mt * 16 + a_row;
                LDSM4(a0[mt][0], a0[mt][1], a0[mt][2], a0[mt][3], A0 + swz(rA, ca));
            }
#pragma unroll
            for (int mt = 0; mt < 2; ++mt) {
                const int rA = wm + mt * 16 + a_row;
                LDSM4(a1[mt][0], a1[mt][1], a1[mt][2], a1[mt][3], A1 + swz(rA, ca));
            }

            // t0: 8 independent MMAs
#pragma unroll
            for (int nt = 0; nt < 4; ++nt)
#pragma unroll
                for (int mt = 0; mt < 2; ++mt)
                    MMA(acc[0][mt][nt], a0[mt], bh[nt]);
            // t1: 8 independent MMAs (reuse bh)
#pragma unroll
            for (int nt = 0; nt < 4; ++nt)
#pragma unroll
                for (int mt = 0; mt < 2; ++mt)
                    MMA(acc[1][mt][nt], a1[mt], bh[nt]);
        }
    }

    // ------------------------------------------------------------ epilogue
    const float b0 = __ldg(&bias[0]);
    const float b1 = __ldg(&bias[1]);
    float2* o2 = reinterpret_cast<float2*>(out) + (size_t)b * Ln * Ln;
    const int r4 = lane >> 2;
    const int c4 = (lane & 3) * 2;

#pragma unroll
    for (int mt = 0; mt < 2; ++mt) {
#pragma unroll
        for (int nt = 0; nt < 4; ++nt) {
            const int i0 = gi0 + wm + mt * 16 + r4;
            const int j0 = gj0 + wn + nt * 8 + c4;
            const float2 p00 = make_float2(acc[0][mt][nt][0] + b0, acc[1][mt][nt][0] + b1);
            const float2 p01 = make_float2(acc[0][mt][nt][1] + b0, acc[1][mt][nt][1] + b1);
            const float2 p10 = make_float2(acc[0][mt][nt][2] + b0, acc[1][mt][nt][2] + b1);
            const float2 p11 = make_float2(acc[0][mt][nt][3] + b0, acc[1][mt][nt][3] + b1);
            o2[(size_t)i0 * Ln + j0]           = p00;
            o2[(size_t)i0 * Ln + j0 + 1]       = p01;
            o2[(size_t)(i0 + 8) * Ln + j0]     = p10;
            o2[(size_t)(i0 + 8) * Ln + j0 + 1] = p11;
            if (mirror) {
                o2[(size_t)j0 * Ln + i0]           = p00;
                o2[(size_t)(j0 + 1) * Ln + i0]     = p01;
                o2[(size_t)j0 * Ln + i0 + 8]       = p10;
                o2[(size_t)(j0 + 1) * Ln + i0 + 8] = p11;
            }
        }
    }
}

// ---------------------------------------------------------------- launch
extern "C" void kernel_launch(void* const* d_in, const int* in_sizes, int n_in,
                              void* d_out, int out_size)
{
    const float* H    = (const float*)d_in[0];
    const float* W    = (const float*)d_in[1];
    const float* bias = (const float*)d_in[2];
    float* out = (float*)d_out;

    cudaFuncSetAttribute(gram_hmma, cudaFuncAttributeMaxDynamicSharedMemorySize, SMEM_DYN);

    cvt_kernel<<<(Bn * Ln * (Dn / 4)) / 256, 256>>>(H, W);

    dim3 grid(NPAIR, Bn);
    gram_hmma<<<grid, 512, SMEM_DYN>>>(bias, out);
}

// round 10
// speedup vs baseline: 2.6345x; 1.1469x over previous
#include <cuda_runtime.h>
#include <cuda_fp16.h>
#include <cstdint>

static constexpr int Bn = 2;
static constexpr int Ln = 2048;
static constexpr int Dn = 1536;
static constexpr int NTILE = Ln / 128;                 // 16
static constexpr int NPAIR = NTILE * (NTILE + 1) / 2;  // 136
static constexpr int BK = 64;                          // k per stage
static constexpr int NSTG = Dn / BK;                   // 24
static constexpr int TILE_B = 128 * BK * 2;            // 16384 B per tile
static constexpr int STAGE_B = 3 * TILE_B;             // A0 + A1 + B = 49152
static constexpr int NSTAGE = 3;
static constexpr int SMEM_DYN = NSTAGE * STAGE_B;      // 147456

// f16 planes: 0..3 = A(b,t) = H*Wp_t  (index b*2+t); 4..5 = B(b) = H (index 4+b)
__device__ __align__(16) __half g_cvt[6ull * Ln * Dn];

// ---------------------------------------------------------------- convert
__global__ __launch_bounds__(256) void cvt_kernel(const float* __restrict__ H,
                                                  const float* __restrict__ W)
{
    const int idx = blockIdx.x * 256 + threadIdx.x;   // Bn*Ln*(Dn/4)
    const int d4  = idx % (Dn / 4);
    const int row = (idx / (Dn / 4)) % Ln;
    const int b   = idx / ((Dn / 4) * Ln);
    const int d0  = d4 * 4;

    const float4 h = *reinterpret_cast<const float4*>(H + ((size_t)b * Ln + row) * Dn + d0);
    const size_t rowoff = (size_t)row * Dn + d0;

#pragma unroll
    for (int t = 0; t < 2; ++t) {
        const float4 w = *reinterpret_cast<const float4*>(W + (size_t)t * (2 * Dn) + d0);
        __half2* p = reinterpret_cast<__half2*>(g_cvt + (size_t)(b * 2 + t) * Ln * Dn + rowoff);
        p[0] = __floats2half2_rn(h.x * w.x, h.y * w.y);
        p[1] = __floats2half2_rn(h.z * w.z, h.w * w.w);
    }
    __half2* q = reinterpret_cast<__half2*>(g_cvt + (size_t)(4 + b) * Ln * Dn + rowoff);
    q[0] = __floats2half2_rn(h.x, h.y);
    q[1] = __floats2half2_rn(h.z, h.w);
}

// ---------------------------------------------------------------- helpers
__device__ __forceinline__ uint32_t s2u(const void* p) {
    uint32_t a;
    asm("{ .reg .u64 t; cvta.to.shared.u64 t, %1; cvt.u32.u64 %0, t; }" : "=r"(a) : "l"(p));
    return a;
}

// swizzled byte offset inside a 128x64(f16) tile (128B rows):
// row*128 + ((c ^ (row & 7)) * 16), c in 0..7
__device__ __forceinline__ uint32_t swz(int row, int c) {
    return (uint32_t)(row * 128 + ((c ^ (row & 7)) << 4));
}

#define LDSM4(R0, R1, R2, R3, addr)                                            \
    asm volatile("ldmatrix.sync.aligned.m8n8.x4.shared.b16 {%0,%1,%2,%3}, [%4];" \
                 : "=r"(R0), "=r"(R1), "=r"(R2), "=r"(R3) : "r"(addr))

#define MMA(C, A, B)                                                              \
    asm volatile(                                                                 \
        "mma.sync.aligned.m16n8k16.row.col.f32.f16.f16.f32 "                      \
        "{%0,%1,%2,%3},{%4,%5,%6,%7},{%8,%9},{%0,%1,%2,%3};"                      \
        : "+f"((C)[0]), "+f"((C)[1]), "+f"((C)[2]), "+f"((C)[3])                  \
        : "r"((A)[0]), "r"((A)[1]), "r"((A)[2]), "r"((A)[3]),                     \
          "r"((B)[0]), "r"((B)[1]))

// ---------------------------------------------------------------- gram GEMM
// 512 threads = 16 warps in 4(m)x4(n), warp tile 32x32 PER t (computes both t)
__global__ __launch_bounds__(512, 1)
void gram_hmma(const float* __restrict__ bias, float* __restrict__ out)
{
    extern __shared__ __align__(1024) char smem_raw[];
    const uint32_t sb = s2u(smem_raw);

    const int tid = threadIdx.x;
    const int wid = tid >> 5;
    const int lane = tid & 31;

    const int wm = (wid >> 2) * 32;   // 0,32,64,96
    const int wn = (wid & 3) * 32;    // 0,32,64,96

    const int a_row = lane & 15;
    const int ak3   = lane >> 4;
    const int b_row = (lane & 7) + (lane >> 4) * 8;
    const int bk3   = (lane >> 3) & 1;

    // decode upper-triangular tile pair (ti <= tj)
    int rem = blockIdx.x, ti = 0, rl = NTILE;
    while (rem >= rl) { rem -= rl; --rl; ++ti; }
    const int tj = ti + rem;
    const int b = blockIdx.y;
    const int gi0 = ti * 128, gj0 = tj * 128;
    const bool mirror = (ti != tj);

    const __half* src[3];
    src[0] = g_cvt + ((size_t)(b * 2 + 0) * Ln + gi0) * Dn;   // A t0
    src[1] = g_cvt + ((size_t)(b * 2 + 1) * Ln + gi0) * Dn;   // A t1
    src[2] = g_cvt + ((size_t)(4 + b) * Ln + gj0) * Dn;       // B

    // 512 threads: 2 chunks of 16B per thread per tile (128 rows x 8 chunks)
    auto load_stage = [&](int s, int buf) {
        const int k0 = s * BK;
        const uint32_t sbase = sb + buf * STAGE_B;
#pragma unroll
        for (int tI = 0; tI < 3; ++tI) {
            const __half* base = src[tI] + k0;
            const uint32_t tb = sbase + tI * TILE_B;
#pragma unroll
            for (int q = 0; q < 2; ++q) {
                const int chunk = tid + 512 * q;
                const int row = chunk >> 3, c = chunk & 7;
                const uint32_t d = tb + swz(row, c);
                const void* g = base + (size_t)row * Dn + c * 8;
                asm volatile("cp.async.cg.shared.global [%0], [%1], 16;"
                             :: "r"(d), "l"(g) : "memory");
            }
        }
        asm volatile("cp.async.commit_group;" ::: "memory");
    };

    float acc[2][2][4][4];
#pragma unroll
    for (int t = 0; t < 2; ++t)
#pragma unroll
        for (int mt = 0; mt < 2; ++mt)
#pragma unroll
            for (int nt = 0; nt < 4; ++nt)
#pragma unroll
                for (int e = 0; e < 4; ++e) acc[t][mt][nt][e] = 0.f;

    load_stage(0, 0);
    load_stage(1, 1);

#pragma unroll 1
    for (int s = 0; s < NSTG; ++s) {
        const int buf = s % NSTAGE;
        if (s == NSTG - 1)
            asm volatile("cp.async.wait_group 0;" ::: "memory");
        else
            asm volatile("cp.async.wait_group 1;" ::: "memory");
        __syncthreads();
        if (s + 2 < NSTG) load_stage(s + 2, (s + 2) % NSTAGE);

        const uint32_t A0 = sb + buf * STAGE_B;
        const uint32_t A1 = A0 + TILE_B;
        const uint32_t Bt = A0 + 2 * TILE_B;

        // fragment pipeline: bh double-buffered; a0/a1 reloaded right after use
        uint32_t bh[2][4][2], a0[2][4], a1[2][4];

        // preload k16 step 0
#pragma unroll
        for (int n2 = 0; n2 < 2; ++n2) {
            const int rB = wn + n2 * 16 + b_row;
            LDSM4(bh[0][n2 * 2][0], bh[0][n2 * 2][1],
                  bh[0][n2 * 2 + 1][0], bh[0][n2 * 2 + 1][1], Bt + swz(rB, bk3));
        }
#pragma unroll
        for (int mt = 0; mt < 2; ++mt) {
            const int rA = wm + mt * 16 + a_row;
            LDSM4(a0[mt][0], a0[mt][1], a0[mt][2], a0[mt][3], A0 + swz(rA, ak3));
            LDSM4(a1[mt][0], a1[mt][1], a1[mt][2], a1[mt][3], A1 + swz(rA, ak3));
        }

#pragma unroll
        for (int s16 = 0; s16 < 4; ++s16) {
            const int cur = s16 & 1;
            // prefetch next step's B fragments
            if (s16 < 3) {
                const int cbn = (s16 + 1) * 2 + bk3;
#pragma unroll
                for (int n2 = 0; n2 < 2; ++n2) {
                    const int rB = wn + n2 * 16 + b_row;
                    LDSM4(bh[cur ^ 1][n2 * 2][0], bh[cur ^ 1][n2 * 2][1],
                          bh[cur ^ 1][n2 * 2 + 1][0], bh[cur ^ 1][n2 * 2 + 1][1],
                          Bt + swz(rB, cbn));
                }
            }

            // t0 MMAs (consume a0)
#pragma unroll
            for (int nt = 0; nt < 4; ++nt)
#pragma unroll
                for (int mt = 0; mt < 2; ++mt)
                    MMA(acc[0][mt][nt], a0[mt], bh[cur][nt]);

            // reload a0 for next step (overlaps t1 MMAs)
            uint32_t a0n[2][4];
            if (s16 < 3) {
                const int can = (s16 + 1) * 2 + ak3;
#pragma unroll
                for (int mt = 0; mt < 2; ++mt) {
                    const int rA = wm + mt * 16 + a_row;
                    LDSM4(a0n[mt][0], a0n[mt][1], a0n[mt][2], a0n[mt][3], A0 + swz(rA, can));
                }
            }

            // t1 MMAs (consume a1, reuse bh[cur])
#pragma unroll
            for (int nt = 0; nt < 4; ++nt)
#pragma unroll
                for (int mt = 0; mt < 2; ++mt)
                    MMA(acc[1][mt][nt], a1[mt], bh[cur][nt]);

            // reload a1 for next step
            if (s16 < 3) {
                const int can = (s16 + 1) * 2 + ak3;
#pragma unroll
                for (int mt = 0; mt < 2; ++mt) {
                    const int rA = wm + mt * 16 + a_row;
                    LDSM4(a1[mt][0], a1[mt][1], a1[mt][2], a1[mt][3], A1 + swz(rA, can));
                }
#pragma unroll
                for (int mt = 0; mt < 2; ++mt)
#pragma unroll
                    for (int e = 0; e < 4; ++e) a0[mt][e] = a0n[mt][e];
            }
        }
    }

    // ------------------------------------------------------------ epilogue
    const float b0 = __ldg(&bias[0]);
    const float b1 = __ldg(&bias[1]);
    float2* o2 = reinterpret_cast<float2*>(out) + (size_t)b * Ln * Ln;
    const int r4 = lane >> 2;
    const int c4 = (lane & 3) * 2;

#pragma unroll
    for (int mt = 0; mt < 2; ++mt) {
#pragma unroll
        for (int nt = 0; nt < 4; ++nt) {
            const int i0 = gi0 + wm + mt * 16 + r4;
            const int j0 = gj0 + wn + nt * 8 + c4;
            const float2 p00 = make_float2(acc[0][mt][nt][0] + b0, acc[1][mt][nt][0] + b1);
            const float2 p01 = make_float2(acc[0][mt][nt][1] + b0, acc[1][mt][nt][1] + b1);
            const float2 p10 = make_float2(acc[0][mt][nt][2] + b0, acc[1][mt][nt][2] + b1);
            const float2 p11 = make_float2(acc[0][mt][nt][3] + b0, acc[1][mt][nt][3] + b1);
            o2[(size_t)i0 * Ln + j0]           = p00;
            o2[(size_t)i0 * Ln + j0 + 1]       = p01;
            o2[(size_t)(i0 + 8) * Ln + j0]     = p10;
            o2[(size_t)(i0 + 8) * Ln + j0 + 1] = p11;
            if (mirror) {
                o2[(size_t)j0 * Ln + i0]           = p00;
                o2[(size_t)(j0 + 1) * Ln + i0]     = p01;
                o2[(size_t)j0 * Ln + i0 + 8]       = p10;
                o2[(size_t)(j0 + 1) * Ln + i0 + 8] = p11;
            }
        }
    }
}

// ---------------------------------------------------------------- launch
extern "C" void kernel_launch(void* const* d_in, const int* in_sizes, int n_in,
                              void* d_out, int out_size)
{
    const float* H    = (const float*)d_in[0];
    const float* W    = (const float*)d_in[1];
    const float* bias = (const float*)d_in[2];
    float* out = (float*)d_out;

    cudaFuncSetAttribute(gram_hmma, cudaFuncAttributeMaxDynamicSharedMemorySize, SMEM_DYN);

    cvt_kernel<<<(Bn * Ln * (Dn / 4)) / 256, 256>>>(H, W);

    dim3 grid(NPAIR, Bn);
    gram_hmma<<<grid, 512, SMEM_DYN>>>(bias, out);
}

// round 11
// speedup vs baseline: 2.8546x; 1.0836x over previous
#include <cuda_runtime.h>
#include <cuda_fp16.h>
#include <cstdint>

static constexpr int Bn = 2;
static constexpr int Ln = 2048;
static constexpr int Dn = 1536;
static constexpr int NCOL = Ln / 128;                  // 16 col-tiles (128 wide)
static constexpr int NPAIR = 272;                      // sum_{j<16}(2j+2)
static constexpr int BK = 64;                          // k per stage
static constexpr int NSTG = Dn / BK;                   // 24
static constexpr int A_TILE_B = 64 * BK * 2;           // 8192  B per A plane (64 rows)
static constexpr int B_TILE_B = 128 * BK * 2;          // 16384 B per B plane (128 rows)
static constexpr int STAGE_B = 2 * A_TILE_B + B_TILE_B;  // 32768
static constexpr int NSTAGE = 3;
static constexpr int SMEM_DYN = NSTAGE * STAGE_B;      // 98304 -> 2 CTAs/SM

// f16 planes: 0..3 = A(b,t) = H*Wp_t  (index b*2+t); 4..5 = B(b) = H (index 4+b)
__device__ __align__(16) __half g_cvt[6ull * Ln * Dn];

// ---------------------------------------------------------------- convert
__global__ __launch_bounds__(256) void cvt_kernel(const float* __restrict__ H,
                                                  const float* __restrict__ W)
{
    const int idx = blockIdx.x * 256 + threadIdx.x;   // Bn*Ln*(Dn/4)
    const int d4  = idx % (Dn / 4);
    const int row = (idx / (Dn / 4)) % Ln;
    const int b   = idx / ((Dn / 4) * Ln);
    const int d0  = d4 * 4;

    const float4 h = *reinterpret_cast<const float4*>(H + ((size_t)b * Ln + row) * Dn + d0);
    const size_t rowoff = (size_t)row * Dn + d0;

#pragma unroll
    for (int t = 0; t < 2; ++t) {
        const float4 w = *reinterpret_cast<const float4*>(W + (size_t)t * (2 * Dn) + d0);
        __half2* p = reinterpret_cast<__half2*>(g_cvt + (size_t)(b * 2 + t) * Ln * Dn + rowoff);
        p[0] = __floats2half2_rn(h.x * w.x, h.y * w.y);
        p[1] = __floats2half2_rn(h.z * w.z, h.w * w.w);
    }
    __half2* q = reinterpret_cast<__half2*>(g_cvt + (size_t)(4 + b) * Ln * Dn + rowoff);
    q[0] = __floats2half2_rn(h.x, h.y);
    q[1] = __floats2half2_rn(h.z, h.w);
}

// ---------------------------------------------------------------- helpers
__device__ __forceinline__ uint32_t s2u(const void* p) {
    uint32_t a;
    asm("{ .reg .u64 t; cvta.to.shared.u64 t, %1; cvt.u32.u64 %0, t; }" : "=r"(a) : "l"(p));
    return a;
}

// swizzled byte offset inside a (rows x 64 f16) tile (128B rows):
// row*128 + ((c ^ (row & 7)) * 16), c in 0..7
__device__ __forceinline__ uint32_t swz(int row, int c) {
    return (uint32_t)(row * 128 + ((c ^ (row & 7)) << 4));
}

#define LDSM4(R0, R1, R2, R3, addr)                                            \
    asm volatile("ldmatrix.sync.aligned.m8n8.x4.shared.b16 {%0,%1,%2,%3}, [%4];" \
                 : "=r"(R0), "=r"(R1), "=r"(R2), "=r"(R3) : "r"(addr))

#define MMA(C, A, B)                                                              \
    asm volatile(                                                                 \
        "mma.sync.aligned.m16n8k16.row.col.f32.f16.f16.f32 "                      \
        "{%0,%1,%2,%3},{%4,%5,%6,%7},{%8,%9},{%0,%1,%2,%3};"                      \
        : "+f"((C)[0]), "+f"((C)[1]), "+f"((C)[2]), "+f"((C)[3])                  \
        : "r"((A)[0]), "r"((A)[1]), "r"((A)[2]), "r"((A)[3]),                     \
          "r"((B)[0]), "r"((B)[1]))

// ---------------------------------------------------------------- gram GEMM
// 256 threads = 8 warps in 2(m)x4(n), warp tile 32x32 PER t, CTA tile 64x128
__global__ __launch_bounds__(256, 2)
void gram_hmma(const float* __restrict__ bias, float* __restrict__ out)
{
    extern __shared__ __align__(1024) char smem_raw[];
    const uint32_t sb = s2u(smem_raw);

    const int tid = threadIdx.x;
    const int wid = tid >> 5;
    const int lane = tid & 31;

    const int wm = (wid >> 2) * 32;   // 0,32
    const int wn = (wid & 3) * 32;    // 0,32,64,96

    const int a_row = lane & 15;
    const int ak3   = lane >> 4;
    const int b_row = (lane & 7) + (lane >> 4) * 8;
    const int bk3   = (lane >> 3) & 1;

    // decode (row-tile i of 64, col-tile j of 128), i in [0, 2j+1]
    int rem = blockIdx.x, j = 0;
    while (rem >= 2 * j + 2) { rem -= 2 * j + 2; ++j; }
    const int i = rem;
    const int b = blockIdx.y;
    const int gi0 = i * 64, gj0 = j * 128;
    const bool mirror = (i < 2 * j);   // strictly above the diagonal 128-block

    const __half* src[3];
    src[0] = g_cvt + ((size_t)(b * 2 + 0) * Ln + gi0) * Dn;   // A t0 (64 rows)
    src[1] = g_cvt + ((size_t)(b * 2 + 1) * Ln + gi0) * Dn;   // A t1 (64 rows)
    src[2] = g_cvt + ((size_t)(4 + b) * Ln + gj0) * Dn;       // B (128 rows)

    auto load_stage = [&](int s, int buf) {
        const int k0 = s * BK;
        const uint32_t sbase = sb + buf * STAGE_B;
        // A planes: 64 rows x 8 chunks = 512 chunks -> 2 per thread each
#pragma unroll
        for (int pI = 0; pI < 2; ++pI) {
            const __half* base = src[pI] + k0;
            const uint32_t tb = sbase + pI * A_TILE_B;
#pragma unroll
            for (int q = 0; q < 2; ++q) {
                const int chunk = tid + 256 * q;
                const int row = chunk >> 3, c = chunk & 7;
                const uint32_t d = tb + swz(row, c);
                const void* g = base + (size_t)row * Dn + c * 8;
                asm volatile("cp.async.cg.shared.global [%0], [%1], 16;"
                             :: "r"(d), "l"(g) : "memory");
            }
        }
        // B plane: 128 rows x 8 chunks = 1024 chunks -> 4 per thread
        {
            const __half* base = src[2] + k0;
            const uint32_t tb = sbase + 2 * A_TILE_B;
#pragma unroll
            for (int q = 0; q < 4; ++q) {
                const int chunk = tid + 256 * q;
                const int row = chunk >> 3, c = chunk & 7;
                const uint32_t d = tb + swz(row, c);
                const void* g = base + (size_t)row * Dn + c * 8;
                asm volatile("cp.async.cg.shared.global [%0], [%1], 16;"
                             :: "r"(d), "l"(g) : "memory");
            }
        }
        asm volatile("cp.async.commit_group;" ::: "memory");
    };

    float acc[2][2][4][4];
#pragma unroll
    for (int t = 0; t < 2; ++t)
#pragma unroll
        for (int mt = 0; mt < 2; ++mt)
#pragma unroll
            for (int nt = 0; nt < 4; ++nt)
#pragma unroll
                for (int e = 0; e < 4; ++e) acc[t][mt][nt][e] = 0.f;

    load_stage(0, 0);
    load_stage(1, 1);

#pragma unroll 1
    for (int s = 0; s < NSTG; ++s) {
        const int buf = s % NSTAGE;
        if (s == NSTG - 1)
            asm volatile("cp.async.wait_group 0;" ::: "memory");
        else
            asm volatile("cp.async.wait_group 1;" ::: "memory");
        __syncthreads();
        if (s + 2 < NSTG) load_stage(s + 2, (s + 2) % NSTAGE);

        const uint32_t A0 = sb + buf * STAGE_B;
        const uint32_t A1 = A0 + A_TILE_B;
        const uint32_t Bt = A0 + 2 * A_TILE_B;

        // fragment pipeline: bh double-buffered; a0/a1 reloaded right after use
        uint32_t bh[2][4][2], a0[2][4], a1[2][4];

#pragma unroll
        for (int n2 = 0; n2 < 2; ++n2) {
            const int rB = wn + n2 * 16 + b_row;
            LDSM4(bh[0][n2 * 2][0], bh[0][n2 * 2][1],
                  bh[0][n2 * 2 + 1][0], bh[0][n2 * 2 + 1][1], Bt + swz(rB, bk3));
        }
#pragma unroll
        for (int mt = 0; mt < 2; ++mt) {
            const int rA = wm + mt * 16 + a_row;
            LDSM4(a0[mt][0], a0[mt][1], a0[mt][2], a0[mt][3], A0 + swz(rA, ak3));
            LDSM4(a1[mt][0], a1[mt][1], a1[mt][2], a1[mt][3], A1 + swz(rA, ak3));
        }

#pragma unroll
        for (int s16 = 0; s16 < 4; ++s16) {
            const int cur = s16 & 1;
            if (s16 < 3) {
                const int cbn = (s16 + 1) * 2 + bk3;
#pragma unroll
                for (int n2 = 0; n2 < 2; ++n2) {
                    const int rB = wn + n2 * 16 + b_row;
                    LDSM4(bh[cur ^ 1][n2 * 2][0], bh[cur ^ 1][n2 * 2][1],
                          bh[cur ^ 1][n2 * 2 + 1][0], bh[cur ^ 1][n2 * 2 + 1][1],
                          Bt + swz(rB, cbn));
                }
            }

            // t0 MMAs
#pragma unroll
            for (int nt = 0; nt < 4; ++nt)
#pragma unroll
                for (int mt = 0; mt < 2; ++mt)
                    MMA(acc[0][mt][nt], a0[mt], bh[cur][nt]);

            uint32_t a0n[2][4];
            if (s16 < 3) {
                const int can = (s16 + 1) * 2 + ak3;
#pragma unroll
                for (int mt = 0; mt < 2; ++mt) {
                    const int rA = wm + mt * 16 + a_row;
                    LDSM4(a0n[mt][0], a0n[mt][1], a0n[mt][2], a0n[mt][3], A0 + swz(rA, can));
                }
            }

            // t1 MMAs (reuse bh[cur])
#pragma unroll
            for (int nt = 0; nt < 4; ++nt)
#pragma unroll
                for (int mt = 0; mt < 2; ++mt)
                    MMA(acc[1][mt][nt], a1[mt], bh[cur][nt]);

            if (s16 < 3) {
                const int can = (s16 + 1) * 2 + ak3;
#pragma unroll
                for (int mt = 0; mt < 2; ++mt) {
                    const int rA = wm + mt * 16 + a_row;
                    LDSM4(a1[mt][0], a1[mt][1], a1[mt][2], a1[mt][3], A1 + swz(rA, can));
                }
#pragma unroll
                for (int mt = 0; mt < 2; ++mt)
#pragma unroll
                    for (int e = 0; e < 4; ++e) a0[mt][e] = a0n[mt][e];
            }
        }
    }

    // ------------------------------------------------------------ epilogue
    const float b0 = __ldg(&bias[0]);
    const float b1 = __ldg(&bias[1]);
    float2* o2 = reinterpret_cast<float2*>(out) + (size_t)b * Ln * Ln;
    const int r4 = lane >> 2;
    const int c4 = (lane & 3) * 2;

#pragma unroll
    for (int mt = 0; mt < 2; ++mt) {
#pragma unroll
        for (int nt = 0; nt < 4; ++nt) {
            const int i0 = gi0 + wm + mt * 16 + r4;
            const int j0 = gj0 + wn + nt * 8 + c4;
            const float2 p00 = make_float2(acc[0][mt][nt][0] + b0, acc[1][mt][nt][0] + b1);
            const float2 p01 = make_float2(acc[0][mt][nt][1] + b0, acc[1][mt][nt][1] + b1);
            const float2 p10 = make_float2(acc[0][mt][nt][2] + b0, acc[1][mt][nt][2] + b1);
            const float2 p11 = make_float2(acc[0][mt][nt][3] + b0, acc[1][mt][nt][3] + b1);
            o2[(size_t)i0 * Ln + j0]           = p00;
            o2[(size_t)i0 * Ln + j0 + 1]       = p01;
            o2[(size_t)(i0 + 8) * Ln + j0]     = p10;
            o2[(size_t)(i0 + 8) * Ln + j0 + 1] = p11;
            if (mirror) {
                o2[(size_t)j0 * Ln + i0]           = p00;
                o2[(size_t)(j0 + 1) * Ln + i0]     = p01;
                o2[(size_t)j0 * Ln + i0 + 8]       = p10;
                o2[(size_t)(j0 + 1) * Ln + i0 + 8] = p11;
            }
        }
    }
}

// ---------------------------------------------------------------- launch
extern "C" void kernel_launch(void* const* d_in, const int* in_sizes, int n_in,
                              void* d_out, int out_size)
{
    const float* H    = (const float*)d_in[0];
    const float* W    = (const float*)d_in[1];
    const float* bias = (const float*)d_in[2];
    float* out = (float*)d_out;

    cudaFuncSetAttribute(gram_hmma, cudaFuncAttributeMaxDynamicSharedMemorySize, SMEM_DYN);

    cvt_kernel<<<(Bn * Ln * (Dn / 4)) / 256, 256>>>(H, W);

    dim3 grid(NPAIR, Bn);
    gram_hmma<<<grid, 256, SMEM_DYN>>>(bias, out);
}

// round 12
// speedup vs baseline: 2.8665x; 1.0042x over previous
#include <cuda_runtime.h>
#include <cuda_fp16.h>
#include <cstdint>

static constexpr int Bn = 2;
static constexpr int Ln = 2048;
static constexpr int Dn = 1536;
static constexpr int NPAIR = 272;                      // sum_{j<16}(2j+2)
static constexpr int BK = 64;                          // k per stage
static constexpr int NSTG = Dn / BK;                   // 24
static constexpr int A_TILE_B = 64 * BK * 2;           // 8192  B per A plane (64 rows)
static constexpr int B_TILE_B = 128 * BK * 2;          // 16384 B per B plane (128 rows)
static constexpr int STAGE_B = 2 * A_TILE_B + B_TILE_B;  // 32768
static constexpr int NSTAGE = 3;
static constexpr int SMEM_DYN = NSTAGE * STAGE_B;      // 98304 -> 2 CTAs/SM

// f16 planes: 0..3 = A(b,t) = H*Wp_t  (index b*2+t); 4..5 = B(b) = H (index 4+b)
__device__ __align__(16) __half g_cvt[6ull * Ln * Dn];

// ---------------------------------------------------------------- convert
__global__ __launch_bounds__(256) void cvt_kernel(const float* __restrict__ H,
                                                  const float* __restrict__ W)
{
    const int idx = blockIdx.x * 256 + threadIdx.x;   // Bn*Ln*(Dn/4)
    const int d4  = idx % (Dn / 4);
    const int row = (idx / (Dn / 4)) % Ln;
    const int b   = idx / ((Dn / 4) * Ln);
    const int d0  = d4 * 4;

    const float4 h = *reinterpret_cast<const float4*>(H + ((size_t)b * Ln + row) * Dn + d0);
    const size_t rowoff = (size_t)row * Dn + d0;

#pragma unroll
    for (int t = 0; t < 2; ++t) {
        const float4 w = *reinterpret_cast<const float4*>(W + (size_t)t * (2 * Dn) + d0);
        __half2* p = reinterpret_cast<__half2*>(g_cvt + (size_t)(b * 2 + t) * Ln * Dn + rowoff);
        p[0] = __floats2half2_rn(h.x * w.x, h.y * w.y);
        p[1] = __floats2half2_rn(h.z * w.z, h.w * w.w);
    }
    __half2* q = reinterpret_cast<__half2*>(g_cvt + (size_t)(4 + b) * Ln * Dn + rowoff);
    q[0] = __floats2half2_rn(h.x, h.y);
    q[1] = __floats2half2_rn(h.z, h.w);
}

// ---------------------------------------------------------------- helpers
__device__ __forceinline__ uint32_t s2u(const void* p) {
    uint32_t a;
    asm("{ .reg .u64 t; cvta.to.shared.u64 t, %1; cvt.u32.u64 %0, t; }" : "=r"(a) : "l"(p));
    return a;
}

// swizzled byte offset inside a (rows x 64 f16) tile (128B rows):
// row*128 + ((c ^ (row & 7)) * 16), c in 0..7
__device__ __forceinline__ uint32_t swz(int row, int c) {
    return (uint32_t)(row * 128 + ((c ^ (row & 7)) << 4));
}

#define LDSM4(R0, R1, R2, R3, addr)                                            \
    asm volatile("ldmatrix.sync.aligned.m8n8.x4.shared.b16 {%0,%1,%2,%3}, [%4];" \
                 : "=r"(R0), "=r"(R1), "=r"(R2), "=r"(R3) : "r"(addr))

#define MMA(C, A, B)                                                              \
    asm volatile(                                                                 \
        "mma.sync.aligned.m16n8k16.row.col.f32.f16.f16.f32 "                      \
        "{%0,%1,%2,%3},{%4,%5,%6,%7},{%8,%9},{%0,%1,%2,%3};"                      \
        : "+f"((C)[0]), "+f"((C)[1]), "+f"((C)[2]), "+f"((C)[3])                  \
        : "r"((A)[0]), "r"((A)[1]), "r"((A)[2]), "r"((A)[3]),                     \
          "r"((B)[0]), "r"((B)[1]))

// ---------------------------------------------------------------- gram GEMM
// 128 threads = 4 warps in 2(m)x2(n); warp tile 32x64 PER t; CTA tile 64x128
__global__ __launch_bounds__(128, 2)
void gram_hmma(const float* __restrict__ bias, float* __restrict__ out)
{
    extern __shared__ __align__(1024) char smem_raw[];
    const uint32_t sb = s2u(smem_raw);

    const int tid = threadIdx.x;
    const int wid = tid >> 5;
    const int lane = tid & 31;

    const int wm = (wid >> 1) * 32;   // 0,32
    const int wn = (wid & 1) * 64;    // 0,64

    const int a_row = lane & 15;
    const int ak3   = lane >> 4;
    const int b_row = (lane & 7) + (lane >> 4) * 8;
    const int bk3   = (lane >> 3) & 1;

    // decode (row-tile i of 64, col-tile j of 128), i in [0, 2j+1]
    int rem = blockIdx.x, j = 0;
    while (rem >= 2 * j + 2) { rem -= 2 * j + 2; ++j; }
    const int i = rem;
    const int b = blockIdx.y;
    const int gi0 = i * 64, gj0 = j * 128;
    const bool mirror = (i < 2 * j);   // strictly above the diagonal 128-block

    const __half* src[3];
    src[0] = g_cvt + ((size_t)(b * 2 + 0) * Ln + gi0) * Dn;   // A t0 (64 rows)
    src[1] = g_cvt + ((size_t)(b * 2 + 1) * Ln + gi0) * Dn;   // A t1 (64 rows)
    src[2] = g_cvt + ((size_t)(4 + b) * Ln + gj0) * Dn;       // B (128 rows)

    auto load_stage = [&](int s, int buf) {
        const int k0 = s * BK;
        const uint32_t sbase = sb + buf * STAGE_B;
        // A planes: 64 rows x 8 chunks = 512 chunks -> 4 per thread each
#pragma unroll
        for (int pI = 0; pI < 2; ++pI) {
            const __half* base = src[pI] + k0;
            const uint32_t tb = sbase + pI * A_TILE_B;
#pragma unroll
            for (int q = 0; q < 4; ++q) {
                const int chunk = tid + 128 * q;
                const int row = chunk >> 3, c = chunk & 7;
                const uint32_t d = tb + swz(row, c);
                const void* g = base + (size_t)row * Dn + c * 8;
                asm volatile("cp.async.cg.shared.global [%0], [%1], 16;"
                             :: "r"(d), "l"(g) : "memory");
            }
        }
        // B plane: 128 rows x 8 chunks = 1024 chunks -> 8 per thread
        {
            const __half* base = src[2] + k0;
            const uint32_t tb = sbase + 2 * A_TILE_B;
#pragma unroll
            for (int q = 0; q < 8; ++q) {
                const int chunk = tid + 128 * q;
                const int row = chunk >> 3, c = chunk & 7;
                const uint32_t d = tb + swz(row, c);
                const void* g = base + (size_t)row * Dn + c * 8;
                asm volatile("cp.async.cg.shared.global [%0], [%1], 16;"
                             :: "r"(d), "l"(g) : "memory");
            }
        }
        asm volatile("cp.async.commit_group;" ::: "memory");
    };

    float acc[2][2][8][4];
#pragma unroll
    for (int t = 0; t < 2; ++t)
#pragma unroll
        for (int mt = 0; mt < 2; ++mt)
#pragma unroll
            for (int nt = 0; nt < 8; ++nt)
#pragma unroll
                for (int e = 0; e < 4; ++e) acc[t][mt][nt][e] = 0.f;

    load_stage(0, 0);
    load_stage(1, 1);

#pragma unroll 1
    for (int s = 0; s < NSTG; ++s) {
        const int buf = s % NSTAGE;
        if (s == NSTG - 1)
            asm volatile("cp.async.wait_group 0;" ::: "memory");
        else
            asm volatile("cp.async.wait_group 1;" ::: "memory");
        __syncthreads();
        if (s + 2 < NSTG) load_stage(s + 2, (s + 2) % NSTAGE);

        const uint32_t A0 = sb + buf * STAGE_B;
        const uint32_t A1 = A0 + A_TILE_B;
        const uint32_t Bt = A0 + 2 * A_TILE_B;

        // fragment pipeline: bh double-buffered; a0/a1 reloaded right after use
        uint32_t bh[2][8][2], a0[2][4], a1[2][4];

#pragma unroll
        for (int n2 = 0; n2 < 4; ++n2) {
            const int rB = wn + n2 * 16 + b_row;
            LDSM4(bh[0][n2 * 2][0], bh[0][n2 * 2][1],
                  bh[0][n2 * 2 + 1][0], bh[0][n2 * 2 + 1][1], Bt + swz(rB, bk3));
        }
#pragma unroll
        for (int mt = 0; mt < 2; ++mt) {
            const int rA = wm + mt * 16 + a_row;
            LDSM4(a0[mt][0], a0[mt][1], a0[mt][2], a0[mt][3], A0 + swz(rA, ak3));
            LDSM4(a1[mt][0], a1[mt][1], a1[mt][2], a1[mt][3], A1 + swz(rA, ak3));
        }

#pragma unroll
        for (int s16 = 0; s16 < 4; ++s16) {
            const int cur = s16 & 1;
            // prefetch next step's B fragments
            if (s16 < 3) {
                const int cbn = (s16 + 1) * 2 + bk3;
#pragma unroll
                for (int n2 = 0; n2 < 4; ++n2) {
                    const int rB = wn + n2 * 16 + b_row;
                    LDSM4(bh[cur ^ 1][n2 * 2][0], bh[cur ^ 1][n2 * 2][1],
                          bh[cur ^ 1][n2 * 2 + 1][0], bh[cur ^ 1][n2 * 2 + 1][1],
                          Bt + swz(rB, cbn));
                }
            }

            // t0 MMAs: 16 independent (consume a0)
#pragma unroll
            for (int nt = 0; nt < 8; ++nt)
#pragma unroll
                for (int mt = 0; mt < 2; ++mt)
                    MMA(acc[0][mt][nt], a0[mt], bh[cur][nt]);

            // a0 fully consumed: reload directly for next step (overlaps t1 MMAs)
            if (s16 < 3) {
                const int can = (s16 + 1) * 2 + ak3;
#pragma unroll
                for (int mt = 0; mt < 2; ++mt) {
                    const int rA = wm + mt * 16 + a_row;
                    LDSM4(a0[mt][0], a0[mt][1], a0[mt][2], a0[mt][3], A0 + swz(rA, can));
                }
            }

            // t1 MMAs: 16 independent (consume a1, reuse bh[cur])
#pragma unroll
            for (int nt = 0; nt < 8; ++nt)
#pragma unroll
                for (int mt = 0; mt < 2; ++mt)
                    MMA(acc[1][mt][nt], a1[mt], bh[cur][nt]);

            if (s16 < 3) {
                const int can = (s16 + 1) * 2 + ak3;
#pragma unroll
                for (int mt = 0; mt < 2; ++mt) {
                    const int rA = wm + mt * 16 + a_row;
                    LDSM4(a1[mt][0], a1[mt][1], a1[mt][2], a1[mt][3], A1 + swz(rA, can));
                }
            }
        }
    }

    // ------------------------------------------------------------ epilogue
    const float b0 = __ldg(&bias[0]);
    const float b1 = __ldg(&bias[1]);
    float2* o2 = reinterpret_cast<float2*>(out) + (size_t)b * Ln * Ln;
    const int r4 = lane >> 2;
    const int c4 = (lane & 3) * 2;

#pragma unroll
    for (int mt = 0; mt < 2; ++mt) {
#pragma unroll
        for (int nt = 0; nt < 8; ++nt) {
            const int i0 = gi0 + wm + mt * 16 + r4;
            const int j0 = gj0 + wn + nt * 8 + c4;
            const float2 p00 = make_float2(acc[0][mt][nt][0] + b0, acc[1][mt][nt][0] + b1);
            const float2 p01 = make_float2(acc[0][mt][nt][1] + b0, acc[1][mt][nt][1] + b1);
            const float2 p10 = make_float2(acc[0][mt][nt][2] + b0, acc[1][mt][nt][2] + b1);
            const float2 p11 = make_float2(acc[0][mt][nt][3] + b0, acc[1][mt][nt][3] + b1);
            o2[(size_t)i0 * Ln + j0]           = p00;
            o2[(size_t)i0 * Ln + j0 + 1]       = p01;
            o2[(size_t)(i0 + 8) * Ln + j0]     = p10;
            o2[(size_t)(i0 + 8) * Ln + j0 + 1] = p11;
            if (mirror) {
                o2[(size_t)j0 * Ln + i0]           = p00;
                o2[(size_t)(j0 + 1) * Ln + i0]     = p01;
                o2[(size_t)j0 * Ln + i0 + 8]       = p10;
                o2[(size_t)(j0 + 1) * Ln + i0 + 8] = p11;
            }
        }
    }
}

// ---------------------------------------------------------------- launch
extern "C" void kernel_launch(void* const* d_in, const int* in_sizes, int n_in,
                              void* d_out, int out_size)
{
    const float* H    = (const float*)d_in[0];
    const float* W    = (const float*)d_in[1];
    const float* bias = (const float*)d_in[2];
    float* out = (float*)d_out;

    cudaFuncSetAttribute(gram_hmma, cudaFuncAttributeMaxDynamicSharedMemorySize, SMEM_DYN);

    cvt_kernel<<<(Bn * Ln * (Dn / 4)) / 256, 256>>>(H, W);

    dim3 grid(NPAIR, Bn);
    gram_hmma<<<grid, 128, SMEM_DYN>>>(bias, out);
}

// round 13
// speedup vs baseline: 3.0870x; 1.0769x over previous
#include <cuda_runtime.h>
#include <cuda_fp16.h>
#include <cstdint>

static constexpr int Bn = 2;
static constexpr int Ln = 2048;
static constexpr int Dn = 1536;
static constexpr int NPAIR = 272;                      // sum_{j<16}(2j+2)
static constexpr int BK = 64;                          // k per stage
static constexpr int NSTG = Dn / BK;                   // 24
static constexpr int NK16 = Dn / 16;                   // 96
static constexpr int A_TILE_B = 64 * BK * 2;           // 8192  (64 rows x 128B)
static constexpr int B_TILE_B = 128 * BK * 2;          // 16384 (128 rows x 128B)
static constexpr int STAGE_B = A_TILE_B + B_TILE_B;    // 24576
static constexpr int NSTAGE = 4;
static constexpr int WTAB_OFF = NSTAGE * STAGE_B;      // 98304
static constexpr int WTAB_B = 2 * NK16 * 4 * 2 * 4;    // 6144 (t,k16,c,e -> __half2)
static constexpr int SMEM_DYN = WTAB_OFF + WTAB_B;     // 104448 -> 2 CTAs/SM

// single f16 plane per batch: g_h16[b][row][d] = rn16(H)
__device__ __align__(16) __half g_h16[2ull * Ln * Dn];

// ---------------------------------------------------------------- convert
__global__ __launch_bounds__(256) void cvt_kernel(const float* __restrict__ H)
{
    const int idx = blockIdx.x * 256 + threadIdx.x;   // Bn*Ln*(Dn/4)
    const int d4  = idx % (Dn / 4);
    const int rb  = idx / (Dn / 4);                   // b*Ln + row
    const int d0  = d4 * 4;

    const float4 h = *reinterpret_cast<const float4*>(H + (size_t)rb * Dn + d0);
    __half2* q = reinterpret_cast<__half2*>(g_h16 + (size_t)rb * Dn + d0);
    q[0] = __floats2half2_rn(h.x, h.y);
    q[1] = __floats2half2_rn(h.z, h.w);
}

// ---------------------------------------------------------------- helpers
__device__ __forceinline__ uint32_t s2u(const void* p) {
    uint32_t a;
    asm("{ .reg .u64 t; cvta.to.shared.u64 t, %1; cvt.u32.u64 %0, t; }" : "=r"(a) : "l"(p));
    return a;
}

// swizzled byte offset inside a (rows x 64 f16) tile (128B rows)
__device__ __forceinline__ uint32_t swz(int row, int c) {
    return (uint32_t)(row * 128 + ((c ^ (row & 7)) << 4));
}

__device__ __forceinline__ uint32_t h2mul(uint32_t a, uint32_t b) {
    __half2 r = __hmul2(*reinterpret_cast<__half2*>(&a), *reinterpret_cast<__half2*>(&b));
    return *reinterpret_cast<uint32_t*>(&r);
}

#define LDSM4(R0, R1, R2, R3, addr)                                            \
    asm volatile("ldmatrix.sync.aligned.m8n8.x4.shared.b16 {%0,%1,%2,%3}, [%4];" \
                 : "=r"(R0), "=r"(R1), "=r"(R2), "=r"(R3) : "r"(addr))

#define MMA(C, A, B)                                                              \
    asm volatile(                                                                 \
        "mma.sync.aligned.m16n8k16.row.col.f32.f16.f16.f32 "                      \
        "{%0,%1,%2,%3},{%4,%5,%6,%7},{%8,%9},{%0,%1,%2,%3};"                      \
        : "+f"((C)[0]), "+f"((C)[1]), "+f"((C)[2]), "+f"((C)[3])                  \
        : "r"((A)[0]), "r"((A)[1]), "r"((A)[2]), "r"((A)[3]),                     \
          "r"((B)[0]), "r"((B)[1]))

// ---------------------------------------------------------------- gram GEMM
// 128 threads = 4 warps in 2(m)x2(n); warp tile 32x64 PER t; CTA tile 64x128
// A_t fragments produced in-register: a_t = a_raw .* w_t[k]
__global__ __launch_bounds__(128, 2)
void gram_hmma(const float* __restrict__ W, const float* __restrict__ bias,
               float* __restrict__ out)
{
    extern __shared__ __align__(1024) char smem_raw[];
    const uint32_t sb = s2u(smem_raw);

    const int tid = threadIdx.x;
    const int wid = tid >> 5;
    const int lane = tid & 31;

    const int wm = (wid >> 1) * 32;   // 0,32
    const int wn = (wid & 1) * 64;    // 0,64

    const int a_row = lane & 15;
    const int ak3   = lane >> 4;
    const int b_row = (lane & 7) + (lane >> 4) * 8;
    const int bk3   = (lane >> 3) & 1;
    const int cquad = lane & 3;       // k-pair selector within fragment

    // decode (row-tile i of 64, col-tile j of 128), i in [0, 2j+1]
    int rem = blockIdx.x, j = 0;
    while (rem >= 2 * j + 2) { rem -= 2 * j + 2; ++j; }
    const int i = rem;
    const int b = blockIdx.y;
    const int gi0 = i * 64, gj0 = j * 128;
    const bool mirror = (i < 2 * j);

    const __half* srcA = g_h16 + ((size_t)b * Ln + gi0) * Dn;   // 64 rows
    const __half* srcB = g_h16 + ((size_t)b * Ln + gj0) * Dn;   // 128 rows

    auto load_stage = [&](int s, int buf) {
        const int k0 = s * BK;
        const uint32_t sbase = sb + buf * STAGE_B;
        // A tile: 64 rows x 8 chunks = 512 -> 4/thread
        {
            const __half* base = srcA + k0;
#pragma unroll
            for (int q = 0; q < 4; ++q) {
                const int chunk = tid + 128 * q;
                const int row = chunk >> 3, c = chunk & 7;
                asm volatile("cp.async.cg.shared.global [%0], [%1], 16;"
                             :: "r"(sbase + swz(row, c)),
                                "l"(base + (size_t)row * Dn + c * 8) : "memory");
            }
        }
        // B tile: 128 rows x 8 chunks = 1024 -> 8/thread
        {
            const __half* base = srcB + k0;
            const uint32_t tb = sbase + A_TILE_B;
#pragma unroll
            for (int q = 0; q < 8; ++q) {
                const int chunk = tid + 128 * q;
                const int row = chunk >> 3, c = chunk & 7;
                asm volatile("cp.async.cg.shared.global [%0], [%1], 16;"
                             :: "r"(tb + swz(row, c)),
                                "l"(base + (size_t)row * Dn + c * 8) : "memory");
            }
        }
        asm volatile("cp.async.commit_group;" ::: "memory");
    };

    // ---- kick off first 3 stage loads
    load_stage(0, 0);
    load_stage(1, 1);
    load_stage(2, 2);

    // ---- build w table in smem: [t][k16][c][e] -> __half2 (w[k], w[k+1])
    // k = k16*16 + e*8 + c*2
    for (int it = 0; it < 12; ++it) {
        const int idx = tid + 128 * it;          // 0..1535
        const int t = idx / 768;
        const int r = idx % 768;
        const int k16 = r >> 3;
        const int c = (r >> 1) & 3;
        const int e = r & 1;
        const int k = k16 * 16 + e * 8 + c * 2;
        const float* wr = W + (size_t)t * (2 * Dn);
        __half2 v = __floats2half2_rn(wr[k], wr[k + 1]);
        asm volatile("st.shared.u32 [%0], %1;"
                     :: "r"(sb + WTAB_OFF + idx * 4),
                        "r"(*reinterpret_cast<uint32_t*>(&v)) : "memory");
    }

    float acc[2][2][8][4];
#pragma unroll
    for (int t = 0; t < 2; ++t)
#pragma unroll
        for (int mt = 0; mt < 2; ++mt)
#pragma unroll
            for (int nt = 0; nt < 8; ++nt)
#pragma unroll
                for (int e = 0; e < 4; ++e) acc[t][mt][nt][e] = 0.f;

    // per-lane w-table address for (t, k16): two __half2 (e=0,1) = LDS.64
    auto waddr = [&](int t, int k16) {
        return sb + WTAB_OFF + (((t * NK16 + k16) * 4 + cquad) * 2) * 4;
    };

#pragma unroll 1
    for (int s = 0; s < NSTG; ++s) {
        const int buf = s % NSTAGE;
        if (s < NSTG - 2)
            asm volatile("cp.async.wait_group 2;" ::: "memory");
        else if (s == NSTG - 2)
            asm volatile("cp.async.wait_group 1;" ::: "memory");
        else
            asm volatile("cp.async.wait_group 0;" ::: "memory");
        __syncthreads();
        if (s + 3 < NSTG) load_stage(s + 3, (s + 3) % NSTAGE);

        const uint32_t At = sb + buf * STAGE_B;
        const uint32_t Bt = At + A_TILE_B;
        const int k16base = s * 4;

        uint32_t bh[2][8][2], araw[2][4];
        uint32_t w0[2][2], w1[2][2];   // [cur][e]

        // preload k16 step 0
#pragma unroll
        for (int n2 = 0; n2 < 4; ++n2) {
            const int rB = wn + n2 * 16 + b_row;
            LDSM4(bh[0][n2 * 2][0], bh[0][n2 * 2][1],
                  bh[0][n2 * 2 + 1][0], bh[0][n2 * 2 + 1][1], Bt + swz(rB, bk3));
        }
#pragma unroll
        for (int mt = 0; mt < 2; ++mt) {
            const int rA = wm + mt * 16 + a_row;
            LDSM4(araw[mt][0], araw[mt][1], araw[mt][2], araw[mt][3], At + swz(rA, ak3));
        }
        asm volatile("ld.shared.v2.u32 {%0,%1}, [%2];"
                     : "=r"(w0[0][0]), "=r"(w0[0][1]) : "r"(waddr(0, k16base)));
        asm volatile("ld.shared.v2.u32 {%0,%1}, [%2];"
                     : "=r"(w1[0][0]), "=r"(w1[0][1]) : "r"(waddr(1, k16base)));

#pragma unroll
        for (int s16 = 0; s16 < 4; ++s16) {
            const int cur = s16 & 1;
            // prefetch next step's B fragments + w pairs
            if (s16 < 3) {
                const int cbn = (s16 + 1) * 2 + bk3;
#pragma unroll
                for (int n2 = 0; n2 < 4; ++n2) {
                    const int rB = wn + n2 * 16 + b_row;
                    LDSM4(bh[cur ^ 1][n2 * 2][0], bh[cur ^ 1][n2 * 2][1],
                          bh[cur ^ 1][n2 * 2 + 1][0], bh[cur ^ 1][n2 * 2 + 1][1],
                          Bt + swz(rB, cbn));
                }
                asm volatile("ld.shared.v2.u32 {%0,%1}, [%2];"
                             : "=r"(w0[cur ^ 1][0]), "=r"(w0[cur ^ 1][1])
                             : "r"(waddr(0, k16base + s16 + 1)));
                asm volatile("ld.shared.v2.u32 {%0,%1}, [%2];"
                             : "=r"(w1[cur ^ 1][0]), "=r"(w1[cur ^ 1][1])
                             : "r"(waddr(1, k16base + s16 + 1)));
            }

            // a0 = araw .* w0 (regs 0,1 use e0; regs 2,3 use e1)
            uint32_t a0[2][4];
#pragma unroll
            for (int mt = 0; mt < 2; ++mt) {
                a0[mt][0] = h2mul(araw[mt][0], w0[cur][0]);
                a0[mt][1] = h2mul(araw[mt][1], w0[cur][0]);
                a0[mt][2] = h2mul(araw[mt][2], w0[cur][1]);
                a0[mt][3] = h2mul(araw[mt][3], w0[cur][1]);
            }

            // t0 MMAs: 16 independent
#pragma unroll
            for (int nt = 0; nt < 8; ++nt)
#pragma unroll
                for (int mt = 0; mt < 2; ++mt)
                    MMA(acc[0][mt][nt], a0[mt], bh[cur][nt]);

            // a1 = araw .* w1, then araw is dead -> reload for next step
            uint32_t a1[2][4];
#pragma unroll
            for (int mt = 0; mt < 2; ++mt) {
                a1[mt][0] = h2mul(araw[mt][0], w1[cur][0]);
                a1[mt][1] = h2mul(araw[mt][1], w1[cur][0]);
                a1[mt][2] = h2mul(araw[mt][2], w1[cur][1]);
                a1[mt][3] = h2mul(araw[mt][3], w1[cur][1]);
            }
            if (s16 < 3) {
                const int can = (s16 + 1) * 2 + ak3;
#pragma unroll
                for (int mt = 0; mt < 2; ++mt) {
                    const int rA = wm + mt * 16 + a_row;
                    LDSM4(araw[mt][0], araw[mt][1], araw[mt][2], araw[mt][3],
                          At + swz(rA, can));
                }
            }

            // t1 MMAs: 16 independent (reuse bh[cur])
#pragma unroll
            for (int nt = 0; nt < 8; ++nt)
#pragma unroll
                for (int mt = 0; mt < 2; ++mt)
                    MMA(acc[1][mt][nt], a1[mt], bh[cur][nt]);
        }
    }

    // ------------------------------------------------------------ epilogue
    const float b0 = __ldg(&bias[0]);
    const float b1 = __ldg(&bias[1]);
    float2* o2 = reinterpret_cast<float2*>(out) + (size_t)b * Ln * Ln;
    const int r4 = lane >> 2;
    const int c4 = (lane & 3) * 2;

#pragma unroll
    for (int mt = 0; mt < 2; ++mt) {
#pragma unroll
        for (int nt = 0; nt < 8; ++nt) {
            const int i0 = gi0 + wm + mt * 16 + r4;
            const int j0 = gj0 + wn + nt * 8 + c4;
            const float2 p00 = make_float2(acc[0][mt][nt][0] + b0, acc[1][mt][nt][0] + b1);
            const float2 p01 = make_float2(acc[0][mt][nt][1] + b0, acc[1][mt][nt][1] + b1);
            const float2 p10 = make_float2(acc[0][mt][nt][2] + b0, acc[1][mt][nt][2] + b1);
            const float2 p11 = make_float2(acc[0][mt][nt][3] + b0, acc[1][mt][nt][3] + b1);
            o2[(size_t)i0 * Ln + j0]           = p00;
            o2[(size_t)i0 * Ln + j0 + 1]       = p01;
            o2[(size_t)(i0 + 8) * Ln + j0]     = p10;
            o2[(size_t)(i0 + 8) * Ln + j0 + 1] = p11;
            if (mirror) {
                o2[(size_t)j0 * Ln + i0]           = p00;
                o2[(size_t)(j0 + 1) * Ln + i0]     = p01;
                o2[(size_t)j0 * Ln + i0 + 8]       = p10;
                o2[(size_t)(j0 + 1) * Ln + i0 + 8] = p11;
            }
        }
    }
}

// ---------------------------------------------------------------- launch
extern "C" void kernel_launch(void* const* d_in, const int* in_sizes, int n_in,
                              void* d_out, int out_size)
{
    const float* H    = (const float*)d_in[0];
    const float* W    = (const float*)d_in[1];
    const float* bias = (const float*)d_in[2];
    float* out = (float*)d_out;

    cudaFuncSetAttribute(gram_hmma, cudaFuncAttributeMaxDynamicSharedMemorySize, SMEM_DYN);

    cvt_kernel<<<(Bn * Ln * (Dn / 4)) / 256, 256>>>(H);

    dim3 grid(NPAIR, Bn);
    gram_hmma<<<grid, 128, SMEM_DYN>>>(W, bias, out);
}